// round 2
// baseline (speedup 1.0000x reference)
#include <cuda_runtime.h>
#include <cstddef>

// Problem constants
constexpr int BATCH = 32;
constexpr int L     = 2048;
constexpr int R     = 1024;   // RNN_SIZE
constexpr int A     = 512;    // ATT_HID
constexpr int CH    = 64;     // L-chunks for weighted sum
constexpr int LC    = L / CH; // 32 l's per chunk
constexpr float MIN_VALUE = -1e8f;

// Scratch (no allocation allowed)
__device__ float g_att_h[BATCH * A];
__device__ float g_scores[BATCH * L];
__device__ float g_weights[BATCH * L];
__device__ __align__(16) float g_part[(size_t)CH * BATCH * R]; // 8 MB partials
__device__ int g_mask_u8;

// ---------------------------------------------------------------------------
// Mask dtype probe: reads first 16384 words (64KB) — safe whether mask is
// uint8 (64KB buffer) or int32 (256KB buffer). int32 bool masks only ever set
// byte 0 of a word; a uint8 mask sets upper bytes with overwhelming probability
// (65536 Bernoulli bytes).
// ---------------------------------------------------------------------------
__global__ void k_detect(const unsigned int* __restrict__ mw) {
    __shared__ unsigned int red[256];
    unsigned int v = 0;
    for (int w = threadIdx.x; w < 16384; w += 256) v |= mw[w];
    red[threadIdx.x] = v;
    __syncthreads();
    for (int o = 128; o > 0; o >>= 1) {
        if (threadIdx.x < o) red[threadIdx.x] |= red[threadIdx.x + o];
        __syncthreads();
    }
    if (threadIdx.x == 0) g_mask_u8 = (red[0] & 0xFFFFFF00u) ? 1 : 0;
}

// ---------------------------------------------------------------------------
// att_h[b,a] = dot(h[b,:], W_h[a,:]) + b_h[a].  One warp per (b,a).
// grid = 2048 blocks x 256 threads (8 warps) -> 16384 warps = 32*512 outputs.
// ---------------------------------------------------------------------------
__global__ void k_att_h(const float* __restrict__ h,
                        const float* __restrict__ Wh,
                        const float* __restrict__ bh) {
    int gw   = blockIdx.x * 8 + (threadIdx.x >> 5);
    int lane = threadIdx.x & 31;
    int b = gw >> 9;        // /512
    int a = gw & 511;
    const float4* h4 = (const float4*)(h + (size_t)b * R);
    const float4* w4 = (const float4*)(Wh + (size_t)a * R);
    float acc = 0.f;
#pragma unroll
    for (int j = 0; j < 8; j++) {
        int i = lane + j * 32;           // 256 float4 per row
        float4 hv = h4[i], wv = w4[i];
        acc += hv.x * wv.x + hv.y * wv.y + hv.z * wv.z + hv.w * wv.w;
    }
#pragma unroll
    for (int o = 16; o > 0; o >>= 1) acc += __shfl_down_sync(0xffffffffu, acc, o);
    if (lane == 0) g_att_h[b * A + a] = acc + bh[a];
}

// Accurate fast tanh: 1 MUFU (EX2) + a few FMAs, rel err ~1e-7.
__device__ __forceinline__ float tanh_fast(float x) {
    float ax = fabsf(x);
    float e  = __expf(-2.0f * ax);           // in (0,1]
    float t  = __fdividef(1.0f - e, 1.0f + e);
    return copysignf(t, x);
}

// ---------------------------------------------------------------------------
// scores[b,l] = sum_a tanh(p[b,l,a] + att_h[b,a]) * W_a[a] + b_a
// One warp per l; 8 warps/block share one b (att_h row + W_a staged in smem).
// grid = 32*256 = 8192 blocks.
// ---------------------------------------------------------------------------
__global__ void k_scores(const float* __restrict__ p,
                         const float* __restrict__ Wa,
                         const float* __restrict__ ba) {
    __shared__ __align__(16) float sa[A];
    __shared__ __align__(16) float sw[A];
    int b  = blockIdx.x >> 8;
    int lg = blockIdx.x & 255;
    int t  = threadIdx.x;
    sa[t]       = g_att_h[b * A + t];
    sa[t + 256] = g_att_h[b * A + t + 256];
    sw[t]       = Wa[t];
    sw[t + 256] = Wa[t + 256];
    __syncthreads();

    int w = t >> 5, lane = t & 31;
    int l = lg * 8 + w;
    const float4* p4 = (const float4*)(p + ((size_t)(b * L + l)) * A);
    const float4* a4 = (const float4*)sa;
    const float4* w4 = (const float4*)sw;

    // Front-batch the 4 global float4 loads for MLP, then do the math.
    float4 pv[4];
#pragma unroll
    for (int j = 0; j < 4; j++) pv[j] = p4[lane + j * 32];

    float acc = 0.f;
#pragma unroll
    for (int j = 0; j < 4; j++) {
        int i = lane + j * 32;           // 128 float4 per row
        float4 av = a4[i], wv = w4[i];
        acc += tanh_fast(pv[j].x + av.x) * wv.x;
        acc += tanh_fast(pv[j].y + av.y) * wv.y;
        acc += tanh_fast(pv[j].z + av.z) * wv.z;
        acc += tanh_fast(pv[j].w + av.w) * wv.w;
    }
#pragma unroll
    for (int o = 16; o > 0; o >>= 1) acc += __shfl_down_sync(0xffffffffu, acc, o);
    if (lane == 0) g_scores[b * L + l] = acc + ba[0];
}

// ---------------------------------------------------------------------------
// Masked softmax over L per batch. One block per b, 256 threads x 8 elems.
// ---------------------------------------------------------------------------
__global__ void k_softmax(const unsigned char* __restrict__ m8,
                          const int* __restrict__ m32) {
    int b = blockIdx.x, t = threadIdx.x;
    int u8 = g_mask_u8;
    __shared__ float red[256];

    float sv[8];
    float mx = -3.4e38f;
#pragma unroll
    for (int k = 0; k < 8; k++) {
        int l = t + k * 256;
        float s = g_scores[b * L + l];
        bool masked = u8 ? (m8[b * L + l] != 0) : (m32[b * L + l] != 0);
        if (masked) s = MIN_VALUE;
        sv[k] = s;
        mx = fmaxf(mx, s);
    }
    red[t] = mx; __syncthreads();
    for (int o = 128; o > 0; o >>= 1) {
        if (t < o) red[t] = fmaxf(red[t], red[t + o]);
        __syncthreads();
    }
    mx = red[0];
    __syncthreads();

    float ev[8];
    float sum = 0.f;
#pragma unroll
    for (int k = 0; k < 8; k++) { ev[k] = __expf(sv[k] - mx); sum += ev[k]; }
    red[t] = sum; __syncthreads();
    for (int o = 128; o > 0; o >>= 1) {
        if (t < o) red[t] += red[t + o];
        __syncthreads();
    }
    float inv = 1.0f / red[0];
#pragma unroll
    for (int k = 0; k < 8; k++) g_weights[b * L + t + k * 256] = ev[k] * inv;
}

// ---------------------------------------------------------------------------
// Weighted sum partials: part[c][b][r] = sum_{l in chunk c} w[b,l]*af[b,l,r].
// grid = (CH, BATCH); 256 threads cover the full 1024-float r row as float4
// -> perfectly coalesced 4KB row reads; 32 independent row loads per thread.
// ---------------------------------------------------------------------------
__global__ void k_wsum(const float* __restrict__ af) {
    int c = blockIdx.x, b = blockIdx.y, t = threadIdx.x;
    __shared__ float sw[LC];
    if (t < LC) sw[t] = g_weights[b * L + c * LC + t];
    __syncthreads();

    const float4* a4 = (const float4*)(af + ((size_t)b * L + (size_t)c * LC) * R);
    float4 acc = make_float4(0.f, 0.f, 0.f, 0.f);
#pragma unroll 8
    for (int j = 0; j < LC; j++) {
        float w  = sw[j];
        float4 v = a4[(size_t)j * (R / 4) + t];
        acc.x += w * v.x; acc.y += w * v.y; acc.z += w * v.z; acc.w += w * v.w;
    }
    ((float4*)(g_part + ((size_t)c * BATCH + b) * R))[t] = acc;
}

// out[b*R + r] = sum_c part[c][b][r]
__global__ void k_reduce(float* __restrict__ out) {
    int g = blockIdx.x * 256 + threadIdx.x;  // 0..32767
    float s = 0.f;
#pragma unroll 8
    for (int c = 0; c < CH; c++) s += g_part[(size_t)c * BATCH * R + g];
    out[g] = s;
}

// ---------------------------------------------------------------------------
extern "C" void kernel_launch(void* const* d_in, const int* in_sizes, int n_in,
                              void* d_out, int out_size) {
    const float* h    = (const float*)d_in[0];
    const float* af   = (const float*)d_in[1];
    const float* p    = (const float*)d_in[2];
    const void*  mask = d_in[3];
    const float* Wh   = (const float*)d_in[4];
    const float* bh   = (const float*)d_in[5];
    const float* Wa   = (const float*)d_in[6];
    const float* ba   = (const float*)d_in[7];
    float* out = (float*)d_out;

    k_detect<<<1, 256>>>((const unsigned int*)mask);
    k_att_h<<<2048, 256>>>(h, Wh, bh);
    k_scores<<<8192, 256>>>(p, Wa, ba);
    k_softmax<<<BATCH, 256>>>((const unsigned char*)mask, (const int*)mask);
    k_wsum<<<dim3(CH, BATCH), 256>>>(af);
    k_reduce<<<BATCH * R / 256, 256>>>(out);
}

// round 3
// speedup vs baseline: 1.1984x; 1.1984x over previous
#include <cuda_runtime.h>
#include <cstddef>

// Problem constants
constexpr int BATCH = 32;
constexpr int L     = 2048;
constexpr int R     = 1024;   // RNN_SIZE
constexpr int A     = 512;    // ATT_HID
constexpr int CH    = 32;     // L-chunks for weighted sum
constexpr int LC    = L / CH; // 64 l's per chunk
constexpr float MIN_VALUE = -1e8f;

// Scratch (no allocation allowed)
__device__ float g_att_h[BATCH * A];
__device__ float g_scores[BATCH * L];            // masked scores
__device__ float g_mx[BATCH];
__device__ float g_inv[BATCH];                   // 1/sum(exp)
__device__ __align__(16) float g_part[(size_t)CH * BATCH * R]; // 4 MB partials
__device__ int g_mask_u8;

__device__ __forceinline__ float4 ldcs4(const float4* p) { return __ldcs(p); }

// ---------------------------------------------------------------------------
// att_h[b,a] = dot(h[b,:], W_h[a,:]) + b_h[a].  One warp per (b,a).
// grid = 2048 work blocks + 1 probe block. Probe scans first 64KB of mask
// (safe for both uint8 [64KB] and int32 [256KB] layouts): int32 bool masks
// only ever set byte 0 of each word; uint8 masks set upper bytes w.h.p.
// ---------------------------------------------------------------------------
__global__ void k_att_h(const float* __restrict__ h,
                        const float* __restrict__ Wh,
                        const float* __restrict__ bh,
                        const unsigned int* __restrict__ mw) {
    if (blockIdx.x == 2048) {   // mask dtype probe
        __shared__ unsigned int red[256];
        unsigned int v = 0;
        for (int w = threadIdx.x; w < 16384; w += 256) v |= mw[w];
        red[threadIdx.x] = v;
        __syncthreads();
        for (int o = 128; o > 0; o >>= 1) {
            if (threadIdx.x < o) red[threadIdx.x] |= red[threadIdx.x + o];
            __syncthreads();
        }
        if (threadIdx.x == 0) g_mask_u8 = (red[0] & 0xFFFFFF00u) ? 1 : 0;
        return;
    }
    int gw   = blockIdx.x * 8 + (threadIdx.x >> 5);
    int lane = threadIdx.x & 31;
    int b = gw >> 9;        // /512
    int a = gw & 511;
    const float4* h4 = (const float4*)(h + (size_t)b * R);
    const float4* w4 = (const float4*)(Wh + (size_t)a * R);
    float acc = 0.f;
#pragma unroll
    for (int j = 0; j < 8; j++) {
        int i = lane + j * 32;           // 256 float4 per row
        float4 hv = h4[i], wv = w4[i];
        acc += hv.x * wv.x + hv.y * wv.y + hv.z * wv.z + hv.w * wv.w;
    }
#pragma unroll
    for (int o = 16; o > 0; o >>= 1) acc += __shfl_down_sync(0xffffffffu, acc, o);
    if (lane == 0) g_att_h[b * A + a] = acc + bh[a];
}

// Accurate fast tanh: 2 MUFU (EX2 + RCP) + FMAs, rel err ~1e-7.
__device__ __forceinline__ float tanh_fast(float x) {
    float ax = fabsf(x);
    float e  = __expf(-2.0f * ax);           // in (0,1]
    float t  = __fdividef(1.0f - e, 1.0f + e);
    return copysignf(t, x);
}

// ---------------------------------------------------------------------------
// scores[b,l] = mask ? MIN : sum_a tanh(p[b,l,a]+att_h[b,a])*W_a[a] + b_a
// One warp per l; 8 warps/block share one b (att_h row + W_a staged in smem).
// ---------------------------------------------------------------------------
__global__ void k_scores(const float* __restrict__ p,
                         const float* __restrict__ Wa,
                         const float* __restrict__ ba,
                         const unsigned char* __restrict__ m8,
                         const int* __restrict__ m32) {
    __shared__ __align__(16) float sa[A];
    __shared__ __align__(16) float sw[A];
    int b  = blockIdx.x >> 8;
    int lg = blockIdx.x & 255;
    int t  = threadIdx.x;
    sa[t]       = g_att_h[b * A + t];
    sa[t + 256] = g_att_h[b * A + t + 256];
    sw[t]       = Wa[t];
    sw[t + 256] = Wa[t + 256];
    __syncthreads();

    int w = t >> 5, lane = t & 31;
    int l = lg * 8 + w;
    const float4* p4 = (const float4*)(p + ((size_t)(b * L + l)) * A);
    const float4* a4 = (const float4*)sa;
    const float4* w4 = (const float4*)sw;

    // Front-batch the 4 global float4 loads (streaming) for MLP.
    float4 pv[4];
#pragma unroll
    for (int j = 0; j < 4; j++) pv[j] = ldcs4(p4 + lane + j * 32);

    float acc = 0.f;
#pragma unroll
    for (int j = 0; j < 4; j++) {
        int i = lane + j * 32;           // 128 float4 per row
        float4 av = a4[i], wv = w4[i];
        acc += tanh_fast(pv[j].x + av.x) * wv.x;
        acc += tanh_fast(pv[j].y + av.y) * wv.y;
        acc += tanh_fast(pv[j].z + av.z) * wv.z;
        acc += tanh_fast(pv[j].w + av.w) * wv.w;
    }
#pragma unroll
    for (int o = 16; o > 0; o >>= 1) acc += __shfl_down_sync(0xffffffffu, acc, o);
    if (lane == 0) {
        int idx = b * L + l;
        bool masked = g_mask_u8 ? (m8[idx] != 0) : (m32[idx] != 0);
        g_scores[idx] = masked ? MIN_VALUE : acc + ba[0];
    }
}

// ---------------------------------------------------------------------------
// Per-batch max + 1/sum(exp(s-mx)). One block per b, 1024 threads x 2 elems.
// ---------------------------------------------------------------------------
__global__ void k_smax() {
    int b = blockIdx.x, t = threadIdx.x;
    int w = t >> 5, lane = t & 31;
    __shared__ float red[32];

    float s0 = g_scores[b * L + t];
    float s1 = g_scores[b * L + t + 1024];
    float mx = fmaxf(s0, s1);
#pragma unroll
    for (int o = 16; o > 0; o >>= 1) mx = fmaxf(mx, __shfl_xor_sync(0xffffffffu, mx, o));
    if (lane == 0) red[w] = mx;
    __syncthreads();
    if (w == 0) {
        float v = red[lane];
#pragma unroll
        for (int o = 16; o > 0; o >>= 1) v = fmaxf(v, __shfl_xor_sync(0xffffffffu, v, o));
        red[lane] = v;
    }
    __syncthreads();
    mx = red[0];
    __syncthreads();

    float sum = __expf(s0 - mx) + __expf(s1 - mx);
#pragma unroll
    for (int o = 16; o > 0; o >>= 1) sum += __shfl_xor_sync(0xffffffffu, sum, o);
    if (lane == 0) red[w] = sum;
    __syncthreads();
    if (t == 0) {
        float v = 0.f;
#pragma unroll
        for (int i = 0; i < 32; i++) v += red[i];
        g_mx[b]  = mx;
        g_inv[b] = 1.0f / v;
    }
}

// ---------------------------------------------------------------------------
// part[c][b][r] = sum_{l in chunk c} exp(s-mx)*inv * af[b,l,r].
// grid = (CH, BATCH); 256 threads cover the 1024-float r row as float4.
// ---------------------------------------------------------------------------
__global__ void k_wsum(const float* __restrict__ af) {
    int c = blockIdx.x, b = blockIdx.y, t = threadIdx.x;
    __shared__ float sw[LC];
    if (t < LC) {
        float s = g_scores[b * L + c * LC + t];
        sw[t] = __expf(s - g_mx[b]) * g_inv[b];
    }
    __syncthreads();

    const float4* a4 = (const float4*)(af + ((size_t)b * L + (size_t)c * LC) * R);
    float4 acc = make_float4(0.f, 0.f, 0.f, 0.f);
#pragma unroll 8
    for (int j = 0; j < LC; j++) {
        float w  = sw[j];
        float4 v = ldcs4(a4 + (size_t)j * (R / 4) + t);
        acc.x += w * v.x; acc.y += w * v.y; acc.z += w * v.z; acc.w += w * v.w;
    }
    ((float4*)(g_part + ((size_t)c * BATCH + b) * R))[t] = acc;
}

// out[b*R + r] = sum_c part[c][b][r]
__global__ void k_reduce(float* __restrict__ out) {
    int g = blockIdx.x * 256 + threadIdx.x;  // 0..32767
    float s = 0.f;
#pragma unroll 8
    for (int c = 0; c < CH; c++) s += g_part[(size_t)c * BATCH * R + g];
    out[g] = s;
}

// ---------------------------------------------------------------------------
extern "C" void kernel_launch(void* const* d_in, const int* in_sizes, int n_in,
                              void* d_out, int out_size) {
    const float* h    = (const float*)d_in[0];
    const float* af   = (const float*)d_in[1];
    const float* p    = (const float*)d_in[2];
    const void*  mask = d_in[3];
    const float* Wh   = (const float*)d_in[4];
    const float* bh   = (const float*)d_in[5];
    const float* Wa   = (const float*)d_in[6];
    const float* ba   = (const float*)d_in[7];
    float* out = (float*)d_out;

    k_att_h<<<2049, 256>>>(h, Wh, bh, (const unsigned int*)mask);
    k_scores<<<8192, 256>>>(p, Wa, ba, (const unsigned char*)mask, (const int*)mask);
    k_smax<<<BATCH, 1024>>>();
    k_wsum<<<dim3(CH, BATCH), 256>>>(af);
    k_reduce<<<BATCH * R / 256, 256>>>(out);
}

// round 5
// speedup vs baseline: 1.2966x; 1.0820x over previous
#include <cuda_runtime.h>
#include <cstddef>

constexpr int BATCH = 32;
constexpr int L     = 2048;
constexpr int R     = 1024;   // RNN_SIZE
constexpr int A     = 512;    // ATT_HID
constexpr int CH    = 32;     // L-chunks for weighted sum
constexpr int LC    = L / CH; // 64 l's per chunk
constexpr float MIN_VALUE = -1e8f;
constexpr unsigned FULL = 0xffffffffu;

// Scratch (no allocation allowed)
__device__ float g_att_h[BATCH * A];
__device__ float g_scores[BATCH * L];
__device__ float g_mx[BATCH];
__device__ float g_inv[BATCH];
__device__ __align__(16) float g_part[(size_t)CH * BATCH * R]; // 4 MB partials
__device__ int g_mask_u8;

__device__ __forceinline__ float4 ldcs4(const float4* p) { return __ldcs(p); }

// ---------------------------------------------------------------------------
// k_att_h: one warp per a, W_h row in registers, loop over b.
// grid = 64 work blocks + 1 mask-dtype probe block.
// Probe scans first 64KB of mask (safe for uint8 [64KB] or int32 [256KB]):
// int32 bool masks only set byte 0 of each word; uint8 sets upper bytes w.h.p.
// ---------------------------------------------------------------------------
__global__ void k_att_h(const float* __restrict__ h,
                        const float* __restrict__ Wh,
                        const float* __restrict__ bh,
                        const unsigned int* __restrict__ mw) {
    if (blockIdx.x == 64) {   // mask dtype probe
        __shared__ unsigned int red[256];
        unsigned int v = 0;
        for (int w = threadIdx.x; w < 16384; w += 256) v |= mw[w];
        red[threadIdx.x] = v;
        __syncthreads();
        for (int o = 128; o > 0; o >>= 1) {
            if (threadIdx.x < o) red[threadIdx.x] |= red[threadIdx.x + o];
            __syncthreads();
        }
        if (threadIdx.x == 0) g_mask_u8 = (red[0] & 0xFFFFFF00u) ? 1 : 0;
        return;
    }
    int wrp  = threadIdx.x >> 5;
    int lane = threadIdx.x & 31;
    int a = blockIdx.x * 8 + wrp;
    const float4* w4 = (const float4*)(Wh + (size_t)a * R);
    float4 wv[8];
#pragma unroll
    for (int j = 0; j < 8; j++) wv[j] = w4[lane + j * 32];
    float bias = bh[a];

    for (int b = 0; b < BATCH; b++) {
        const float4* h4 = (const float4*)(h + (size_t)b * R);
        float acc = 0.f;
#pragma unroll
        for (int j = 0; j < 8; j++) {
            float4 hv = __ldg(h4 + lane + j * 32);
            acc += hv.x * wv[j].x + hv.y * wv[j].y + hv.z * wv[j].z + hv.w * wv[j].w;
        }
#pragma unroll
        for (int o = 16; o > 0; o >>= 1) acc += __shfl_down_sync(FULL, acc, o);
        if (lane == 0) g_att_h[b * A + a] = acc + bias;
    }
}

// Accurate fast tanh: 2 MUFU (EX2 + RCP) + FMAs, rel err ~1e-7.
__device__ __forceinline__ float tanh_fast(float x) {
    float ax = fabsf(x);
    float e  = __expf(-2.0f * ax);
    float t  = __fdividef(1.0f - e, 1.0f + e);
    return copysignf(t, x);
}

// ---------------------------------------------------------------------------
// scores: masked warps skip the p-row entirely (~50% of the 128MB stream).
// One warp per l; 8 warps/block share one b.
// ---------------------------------------------------------------------------
__global__ void k_scores(const float* __restrict__ p,
                         const float* __restrict__ Wa,
                         const float* __restrict__ ba,
                         const unsigned char* __restrict__ m8,
                         const int* __restrict__ m32) {
    __shared__ __align__(16) float sa[A];
    __shared__ __align__(16) float sw[A];
    int b  = blockIdx.x >> 8;
    int lg = blockIdx.x & 255;
    int t  = threadIdx.x;
    sa[t]       = g_att_h[b * A + t];
    sa[t + 256] = g_att_h[b * A + t + 256];
    sw[t]       = Wa[t];
    sw[t + 256] = Wa[t + 256];
    __syncthreads();

    int w = t >> 5, lane = t & 31;
    int l = lg * 8 + w;
    int idx = b * L + l;

    // Uniform per-warp mask check BEFORE touching p.
    int masked = 0;
    if (lane == 0)
        masked = g_mask_u8 ? (m8[idx] != 0) : (m32[idx] != 0);
    masked = __shfl_sync(FULL, masked, 0);
    if (masked) {
        if (lane == 0) g_scores[idx] = MIN_VALUE;
        return;
    }

    const float4* p4 = (const float4*)(p + (size_t)idx * A);
    const float4* a4 = (const float4*)sa;
    const float4* w4 = (const float4*)sw;

    float4 pv[4];
#pragma unroll
    for (int j = 0; j < 4; j++) pv[j] = ldcs4(p4 + lane + j * 32);

    float acc = 0.f;
#pragma unroll
    for (int j = 0; j < 4; j++) {
        int i = lane + j * 32;
        float4 av = a4[i], wv = w4[i];
        acc += tanh_fast(pv[j].x + av.x) * wv.x;
        acc += tanh_fast(pv[j].y + av.y) * wv.y;
        acc += tanh_fast(pv[j].z + av.z) * wv.z;
        acc += tanh_fast(pv[j].w + av.w) * wv.w;
    }
#pragma unroll
    for (int o = 16; o > 0; o >>= 1) acc += __shfl_down_sync(FULL, acc, o);
    if (lane == 0) g_scores[idx] = acc + ba[0];
}

// ---------------------------------------------------------------------------
// Per-batch max + 1/sum(exp(s-mx)). One block per b, 1024 threads x 2 elems.
// ---------------------------------------------------------------------------
__global__ void k_smax() {
    int b = blockIdx.x, t = threadIdx.x;
    int w = t >> 5, lane = t & 31;
    __shared__ float red[32];

    float s0 = g_scores[b * L + t];
    float s1 = g_scores[b * L + t + 1024];
    float mx = fmaxf(s0, s1);
#pragma unroll
    for (int o = 16; o > 0; o >>= 1) mx = fmaxf(mx, __shfl_xor_sync(FULL, mx, o));
    if (lane == 0) red[w] = mx;
    __syncthreads();
    if (w == 0) {
        float v = red[lane];
#pragma unroll
        for (int o = 16; o > 0; o >>= 1) v = fmaxf(v, __shfl_xor_sync(FULL, v, o));
        red[lane] = v;
    }
    __syncthreads();
    mx = red[0];
    __syncthreads();

    float sum = __expf(s0 - mx) + __expf(s1 - mx);
#pragma unroll
    for (int o = 16; o > 0; o >>= 1) sum += __shfl_xor_sync(FULL, sum, o);
    if (lane == 0) red[w] = sum;
    __syncthreads();
    if (t == 0) {
        float v = 0.f;
#pragma unroll
        for (int i = 0; i < 32; i++) v += red[i];
        g_mx[b]  = mx;
        g_inv[b] = 1.0f / v;
    }
}

// ---------------------------------------------------------------------------
// Weighted-sum partials with zero-weight row skipping.
// Masked l's have w = exp(-1e8 - mx)*inv == 0.0f exactly (underflow; mx >=
// -1e8 so the exponent is <= -9.9e7), and the reference computes the same
// 0.0f contribution -> skipping is bit-exact.
// Warp 0 ballot-compacts nonzero (w, l) pairs so the main loop issues dense,
// unconditional, 4-wide-batched float4 loads (full MLP).
// ---------------------------------------------------------------------------
__global__ void k_wsum(const float* __restrict__ af) {
    int c = blockIdx.x, b = blockIdx.y, t = threadIdx.x;
    __shared__ float swraw[LC];
    __shared__ float swv[LC];
    __shared__ int   sidx[LC];
    __shared__ int   scount;

    int lbase = b * L + c * LC;
    if (t < LC) {
        float s = g_scores[lbase + t];
        swraw[t] = __expf(s - g_mx[b]) * g_inv[b];
    }
    __syncthreads();

    if (t < 32) {
        int base = 0;
#pragma unroll
        for (int k = 0; k < LC; k += 32) {
            float w = swraw[k + t];
            unsigned m = __ballot_sync(FULL, w != 0.f);
            if (w != 0.f) {
                int pos = base + __popc(m & ((1u << t) - 1u));
                swv[pos]  = w;
                sidx[pos] = k + t;
            }
            base += __popc(m);
        }
        if (t == 0) scount = base;
    }
    __syncthreads();

    const float4* a4 = (const float4*)(af + (size_t)lbase * R);
    float4 acc = make_float4(0.f, 0.f, 0.f, 0.f);
    int n = scount;
    int j = 0;
    for (; j + 4 <= n; j += 4) {
        float w0 = swv[j],     w1 = swv[j + 1];
        float w2 = swv[j + 2], w3 = swv[j + 3];
        float4 v0 = ldcs4(a4 + (size_t)sidx[j]     * (R / 4) + t);
        float4 v1 = ldcs4(a4 + (size_t)sidx[j + 1] * (R / 4) + t);
        float4 v2 = ldcs4(a4 + (size_t)sidx[j + 2] * (R / 4) + t);
        float4 v3 = ldcs4(a4 + (size_t)sidx[j + 3] * (R / 4) + t);
        acc.x += w0 * v0.x; acc.y += w0 * v0.y; acc.z += w0 * v0.z; acc.w += w0 * v0.w;
        acc.x += w1 * v1.x; acc.y += w1 * v1.y; acc.z += w1 * v1.z; acc.w += w1 * v1.w;
        acc.x += w2 * v2.x; acc.y += w2 * v2.y; acc.z += w2 * v2.z; acc.w += w2 * v2.w;
        acc.x += w3 * v3.x; acc.y += w3 * v3.y; acc.z += w3 * v3.z; acc.w += w3 * v3.w;
    }
    for (; j < n; j++) {
        float w  = swv[j];
        float4 v = ldcs4(a4 + (size_t)sidx[j] * (R / 4) + t);
        acc.x += w * v.x; acc.y += w * v.y; acc.z += w * v.z; acc.w += w * v.w;
    }
    ((float4*)(g_part + ((size_t)c * BATCH + b) * R))[t] = acc;
}

// out[b*R + r] = sum_c part[c][b][r]
__global__ void k_reduce(float* __restrict__ out) {
    int g = blockIdx.x * 256 + threadIdx.x;
    float s = 0.f;
#pragma unroll 8
    for (int c = 0; c < CH; c++) s += g_part[(size_t)c * BATCH * R + g];
    out[g] = s;
}

// ---------------------------------------------------------------------------
extern "C" void kernel_launch(void* const* d_in, const int* in_sizes, int n_in,
                              void* d_out, int out_size) {
    const float* h    = (const float*)d_in[0];
    const float* af   = (const float*)d_in[1];
    const float* p    = (const float*)d_in[2];
    const void*  mask = d_in[3];
    const float* Wh   = (const float*)d_in[4];
    const float* bh   = (const float*)d_in[5];
    const float* Wa   = (const float*)d_in[6];
    const float* ba   = (const float*)d_in[7];
    float* out = (float*)d_out;

    k_att_h<<<65, 256>>>(h, Wh, bh, (const unsigned int*)mask);
    k_scores<<<8192, 256>>>(p, Wa, ba, (const unsigned char*)mask, (const int*)mask);
    k_smax<<<BATCH, 1024>>>();
    k_wsum<<<dim3(CH, BATCH), 256>>>(af);
    k_reduce<<<BATCH * R / 256, 256>>>(out);
}

// round 6
// speedup vs baseline: 1.6518x; 1.2740x over previous
#include <cuda_runtime.h>
#include <cstddef>

constexpr int BATCH = 32;
constexpr int L     = 2048;
constexpr int R     = 1024;   // RNN_SIZE
constexpr int A     = 512;    // ATT_HID
constexpr int CH    = 16;     // L-chunks for weighted sum
constexpr int LC    = L / CH; // 128 l's per chunk
constexpr float MIN_VALUE = -1e8f;
constexpr unsigned FULL = 0xffffffffu;

// Scratch (no allocation allowed)
__device__ float g_att_h[BATCH * A];
__device__ float g_scores[BATCH * L];
__device__ int   g_lidx[BATCH * L];   // per-b compacted unmasked l indices
__device__ int   g_lcnt[BATCH];
__device__ float g_mx[BATCH];
__device__ float g_inv[BATCH];
__device__ __align__(16) float g_part[(size_t)CH * BATCH * R]; // 2 MB partials
__device__ int g_mask_u8;

__device__ __forceinline__ float4 ldcs4(const float4* p) { return __ldcs(p); }

// ---------------------------------------------------------------------------
// k_att_h: one warp per (a, b-octet). 256 work blocks + 1 mask-dtype probe.
// Probe scans first 64KB of mask (safe for uint8 [64KB] or int32 [256KB]):
// int32 bool masks only set byte 0 of each word; uint8 sets upper bytes w.h.p.
// ---------------------------------------------------------------------------
__global__ void k_att_h(const float* __restrict__ h,
                        const float* __restrict__ Wh,
                        const float* __restrict__ bh,
                        const unsigned int* __restrict__ mw) {
    if (blockIdx.x == 256) {   // mask dtype probe
        __shared__ unsigned int red[256];
        unsigned int v = 0;
        for (int w = threadIdx.x; w < 16384; w += 256) v |= mw[w];
        red[threadIdx.x] = v;
        __syncthreads();
        for (int o = 128; o > 0; o >>= 1) {
            if (threadIdx.x < o) red[threadIdx.x] |= red[threadIdx.x + o];
            __syncthreads();
        }
        if (threadIdx.x == 0) g_mask_u8 = (red[0] & 0xFFFFFF00u) ? 1 : 0;
        return;
    }
    int wrp  = threadIdx.x >> 5;
    int lane = threadIdx.x & 31;
    int gw   = blockIdx.x * 8 + wrp;      // 0..2047
    int a    = gw & 511;
    int bg   = gw >> 9;                    // b-octet 0..3
    const float4* w4 = (const float4*)(Wh + (size_t)a * R);
    float4 wv[8];
#pragma unroll
    for (int j = 0; j < 8; j++) wv[j] = w4[lane + j * 32];
    float bias = bh[a];

#pragma unroll
    for (int bb = 0; bb < 8; bb++) {
        int b = bg * 8 + bb;
        const float4* h4 = (const float4*)(h + (size_t)b * R);
        float acc = 0.f;
#pragma unroll
        for (int j = 0; j < 8; j++) {
            float4 hv = __ldg(h4 + lane + j * 32);
            acc += hv.x * wv[j].x + hv.y * wv[j].y + hv.z * wv[j].z + hv.w * wv[j].w;
        }
#pragma unroll
        for (int o = 16; o > 0; o >>= 1) acc += __shfl_down_sync(FULL, acc, o);
        if (lane == 0) g_att_h[b * A + a] = acc + bias;
    }
}

// ---------------------------------------------------------------------------
// k_compact: per b, build ordered list of unmasked l's; pre-fill scores row
// with MIN_VALUE (k_scores overwrites unmasked entries). One block per b.
// Warp 0 does the ballot compaction; warps 1..7 fill the score row.
// ---------------------------------------------------------------------------
__global__ void k_compact(const unsigned char* __restrict__ m8,
                          const int* __restrict__ m32) {
    int b = blockIdx.x, t = threadIdx.x;
    int w = t >> 5, lane = t & 31;
    int u8 = g_mask_u8;

    if (w == 0) {
        int base = 0;
        for (int k = 0; k < L; k += 32) {
            int idx = b * L + k + lane;
            bool keep = u8 ? (m8[idx] == 0) : (m32[idx] == 0);
            unsigned m = __ballot_sync(FULL, keep);
            if (keep) {
                int pos = base + __popc(m & ((1u << lane) - 1u));
                g_lidx[b * L + pos] = k + lane;
            }
            base += __popc(m);
        }
        if (lane == 0) g_lcnt[b] = base;
    } else {
        for (int i = t - 32; i < L; i += 224)
            g_scores[b * L + i] = MIN_VALUE;
    }
}

// Accurate fast tanh: 2 MUFU (EX2 + RCP) + FMAs, rel err ~1e-7.
__device__ __forceinline__ float tanh_fast(float x) {
    float ax = fabsf(x);
    float e  = __expf(-2.0f * ax);
    float t  = __fdividef(1.0f - e, 1.0f + e);
    return copysignf(t, x);
}

// ---------------------------------------------------------------------------
// scores over the COMPACT list only: block jg covers list slots jg*8..jg*8+7
// of batch b. Blocks past the count exit on one uniform load; all surviving
// warps do full-width work (no intra-block imbalance).
// ---------------------------------------------------------------------------
__global__ void k_scores(const float* __restrict__ p,
                         const float* __restrict__ Wa,
                         const float* __restrict__ ba) {
    int b  = blockIdx.x >> 8;
    int jg = blockIdx.x & 255;
    int cnt = g_lcnt[b];
    if (jg * 8 >= cnt) return;

    __shared__ __align__(16) float sa[A];
    __shared__ __align__(16) float sw[A];
    int t = threadIdx.x;
    sa[t]       = g_att_h[b * A + t];
    sa[t + 256] = g_att_h[b * A + t + 256];
    sw[t]       = Wa[t];
    sw[t + 256] = Wa[t + 256];
    __syncthreads();

    int w = t >> 5, lane = t & 31;
    int j = jg * 8 + w;
    if (j >= cnt) return;
    int l = 0;
    if (lane == 0) l = g_lidx[b * L + j];
    l = __shfl_sync(FULL, l, 0);
    int idx = b * L + l;

    const float4* p4 = (const float4*)(p + (size_t)idx * A);
    const float4* a4 = (const float4*)sa;
    const float4* w4 = (const float4*)sw;

    float4 pv[4];
#pragma unroll
    for (int j2 = 0; j2 < 4; j2++) pv[j2] = ldcs4(p4 + lane + j2 * 32);

    float acc = 0.f;
#pragma unroll
    for (int j2 = 0; j2 < 4; j2++) {
        int i = lane + j2 * 32;
        float4 av = a4[i], wv = w4[i];
        acc += tanh_fast(pv[j2].x + av.x) * wv.x;
        acc += tanh_fast(pv[j2].y + av.y) * wv.y;
        acc += tanh_fast(pv[j2].z + av.z) * wv.z;
        acc += tanh_fast(pv[j2].w + av.w) * wv.w;
    }
#pragma unroll
    for (int o = 16; o > 0; o >>= 1) acc += __shfl_down_sync(FULL, acc, o);
    if (lane == 0) g_scores[idx] = acc + ba[0];
}

// ---------------------------------------------------------------------------
// Per-batch max + 1/sum(exp(s-mx)). One block per b, 1024 threads x 2 elems.
// ---------------------------------------------------------------------------
__global__ void k_smax() {
    int b = blockIdx.x, t = threadIdx.x;
    int w = t >> 5, lane = t & 31;
    __shared__ float red[32];

    float s0 = g_scores[b * L + t];
    float s1 = g_scores[b * L + t + 1024];
    float mx = fmaxf(s0, s1);
#pragma unroll
    for (int o = 16; o > 0; o >>= 1) mx = fmaxf(mx, __shfl_xor_sync(FULL, mx, o));
    if (lane == 0) red[w] = mx;
    __syncthreads();
    if (w == 0) {
        float v = red[lane];
#pragma unroll
        for (int o = 16; o > 0; o >>= 1) v = fmaxf(v, __shfl_xor_sync(FULL, v, o));
        red[lane] = v;
    }
    __syncthreads();
    mx = red[0];
    __syncthreads();

    float sum = __expf(s0 - mx) + __expf(s1 - mx);
#pragma unroll
    for (int o = 16; o > 0; o >>= 1) sum += __shfl_xor_sync(FULL, sum, o);
    if (lane == 0) red[w] = sum;
    __syncthreads();
    if (t == 0) {
        float v = 0.f;
#pragma unroll
        for (int i = 0; i < 32; i++) v += red[i];
        g_mx[b]  = mx;
        g_inv[b] = 1.0f / v;
    }
}

// ---------------------------------------------------------------------------
// Weighted-sum partials with zero-weight row skipping (masked weights
// underflow to exact 0.0f; reference contributes the same 0.0f -> bit-exact).
// Warp 0 ballot-compacts nonzero (w, l) pairs; dense 4-wide-batched loads.
// ---------------------------------------------------------------------------
__global__ void k_wsum(const float* __restrict__ af) {
    int c = blockIdx.x, b = blockIdx.y, t = threadIdx.x;
    __shared__ float swraw[LC];
    __shared__ float swv[LC];
    __shared__ int   sidx[LC];
    __shared__ int   scount;

    int lbase = b * L + c * LC;
    if (t < LC) {
        float s = g_scores[lbase + t];
        swraw[t] = __expf(s - g_mx[b]) * g_inv[b];
    }
    __syncthreads();

    if (t < 32) {
        int base = 0;
#pragma unroll
        for (int k = 0; k < LC; k += 32) {
            float w = swraw[k + t];
            unsigned m = __ballot_sync(FULL, w != 0.f);
            if (w != 0.f) {
                int pos = base + __popc(m & ((1u << t) - 1u));
                swv[pos]  = w;
                sidx[pos] = k + t;
            }
            base += __popc(m);
        }
        if (t == 0) scount = base;
    }
    __syncthreads();

    const float4* a4 = (const float4*)(af + (size_t)lbase * R);
    float4 acc = make_float4(0.f, 0.f, 0.f, 0.f);
    int n = scount;
    int j = 0;
    for (; j + 4 <= n; j += 4) {
        float w0 = swv[j],     w1 = swv[j + 1];
        float w2 = swv[j + 2], w3 = swv[j + 3];
        float4 v0 = ldcs4(a4 + (size_t)sidx[j]     * (R / 4) + t);
        float4 v1 = ldcs4(a4 + (size_t)sidx[j + 1] * (R / 4) + t);
        float4 v2 = ldcs4(a4 + (size_t)sidx[j + 2] * (R / 4) + t);
        float4 v3 = ldcs4(a4 + (size_t)sidx[j + 3] * (R / 4) + t);
        acc.x += w0 * v0.x; acc.y += w0 * v0.y; acc.z += w0 * v0.z; acc.w += w0 * v0.w;
        acc.x += w1 * v1.x; acc.y += w1 * v1.y; acc.z += w1 * v1.z; acc.w += w1 * v1.w;
        acc.x += w2 * v2.x; acc.y += w2 * v2.y; acc.z += w2 * v2.z; acc.w += w2 * v2.w;
        acc.x += w3 * v3.x; acc.y += w3 * v3.y; acc.z += w3 * v3.z; acc.w += w3 * v3.w;
    }
    for (; j < n; j++) {
        float w  = swv[j];
        float4 v = ldcs4(a4 + (size_t)sidx[j] * (R / 4) + t);
        acc.x += w * v.x; acc.y += w * v.y; acc.z += w * v.z; acc.w += w * v.w;
    }
    ((float4*)(g_part + ((size_t)c * BATCH + b) * R))[t] = acc;
}

// out[b*R + r] = sum_c part[c][b][r]
__global__ void k_reduce(float* __restrict__ out) {
    int g = blockIdx.x * 256 + threadIdx.x;
    float s = 0.f;
#pragma unroll 8
    for (int c = 0; c < CH; c++) s += g_part[(size_t)c * BATCH * R + g];
    out[g] = s;
}

// ---------------------------------------------------------------------------
extern "C" void kernel_launch(void* const* d_in, const int* in_sizes, int n_in,
                              void* d_out, int out_size) {
    const float* h    = (const float*)d_in[0];
    const float* af   = (const float*)d_in[1];
    const float* p    = (const float*)d_in[2];
    const void*  mask = d_in[3];
    const float* Wh   = (const float*)d_in[4];
    const float* bh   = (const float*)d_in[5];
    const float* Wa   = (const float*)d_in[6];
    const float* ba   = (const float*)d_in[7];
    float* out = (float*)d_out;

    k_att_h<<<257, 256>>>(h, Wh, bh, (const unsigned int*)mask);
    k_compact<<<BATCH, 256>>>((const unsigned char*)mask, (const int*)mask);
    k_scores<<<8192, 256>>>(p, Wa, ba);
    k_smax<<<BATCH, 1024>>>();
    k_wsum<<<dim3(CH, BATCH), 256>>>(af);
    k_reduce<<<BATCH * R / 256, 256>>>(out);
}

// round 8
// speedup vs baseline: 1.7618x; 1.0666x over previous
#include <cuda_runtime.h>
#include <cstddef>

constexpr int BATCH = 32;
constexpr int L     = 2048;
constexpr int R     = 1024;   // RNN_SIZE
constexpr int A     = 512;    // ATT_HID
constexpr int CH    = 16;     // L-chunks for weighted sum
constexpr int LC    = L / CH; // 128 l's per chunk
constexpr int SC    = 8;      // smax chunks per batch
constexpr int SLEN  = L / SC; // 256 scores per smax block
constexpr float MIN_VALUE = -1e8f;
constexpr unsigned FULL = 0xffffffffu;

// Scratch (no allocation allowed; __device__ globals zero-initialized)
__device__ float g_att_h[BATCH * A];
__device__ float g_scores[BATCH * L];
__device__ int   g_lidx[BATCH * L];       // per-b compacted unmasked l indices
__device__ int   g_lcnt[BATCH];
__device__ float g_pmx[BATCH * SC];       // partial max
__device__ float g_ps[BATCH * SC];        // partial sum(exp(s - pmx))
__device__ __align__(16) float g_part[(size_t)CH * BATCH * R]; // 2 MB partials
__device__ int   g_cnt[BATCH];            // completion counters (self-resetting)
__device__ int   g_mask_u8;

__device__ __forceinline__ float4 ldcs4(const float4* p) { return __ldcs(p); }
__device__ __forceinline__ float4 ldcg4(const float4* p) { return __ldcg(p); }

// ---------------------------------------------------------------------------
// k_att_h: one warp per (a, b-octet). 256 work blocks + 1 mask-dtype probe.
// Probe scans first 64KB of mask (safe for uint8 [64KB] or int32 [256KB]):
// int32 bool masks only set byte 0 of each word; uint8 sets upper bytes w.h.p.
// ---------------------------------------------------------------------------
__global__ void k_att_h(const float* __restrict__ h,
                        const float* __restrict__ Wh,
                        const float* __restrict__ bh,
                        const unsigned int* __restrict__ mw) {
    if (blockIdx.x == 256) {   // mask dtype probe
        __shared__ unsigned int red[256];
        unsigned int v = 0;
        for (int w = threadIdx.x; w < 16384; w += 256) v |= mw[w];
        red[threadIdx.x] = v;
        __syncthreads();
        for (int o = 128; o > 0; o >>= 1) {
            if (threadIdx.x < o) red[threadIdx.x] |= red[threadIdx.x + o];
            __syncthreads();
        }
        if (threadIdx.x == 0) g_mask_u8 = (red[0] & 0xFFFFFF00u) ? 1 : 0;
        return;
    }
    int wrp  = threadIdx.x >> 5;
    int lane = threadIdx.x & 31;
    int gw   = blockIdx.x * 8 + wrp;      // 0..2047
    int a    = gw & 511;
    int bg   = gw >> 9;                    // b-octet 0..3
    const float4* w4 = (const float4*)(Wh + (size_t)a * R);
    float4 wv[8];
#pragma unroll
    for (int j = 0; j < 8; j++) wv[j] = w4[lane + j * 32];
    float bias = bh[a];

#pragma unroll
    for (int bb = 0; bb < 8; bb++) {
        int b = bg * 8 + bb;
        const float4* h4 = (const float4*)(h + (size_t)b * R);
        float acc = 0.f;
#pragma unroll
        for (int j = 0; j < 8; j++) {
            float4 hv = __ldg(h4 + lane + j * 32);
            acc += hv.x * wv[j].x + hv.y * wv[j].y + hv.z * wv[j].z + hv.w * wv[j].w;
        }
#pragma unroll
        for (int o = 16; o > 0; o >>= 1) acc += __shfl_down_sync(FULL, acc, o);
        if (lane == 0) g_att_h[b * A + a] = acc + bias;
    }
}

// ---------------------------------------------------------------------------
// k_compact: per b, ordered list of unmasked l's + MIN_VALUE pre-fill of
// masked score slots. 8 warps each compact a 256-l segment (two-pass ballot
// with smem prefix across warps).
// ---------------------------------------------------------------------------
__global__ void k_compact(const unsigned char* __restrict__ m8,
                          const int* __restrict__ m32) {
    int b = blockIdx.x, t = threadIdx.x;
    int w = t >> 5, lane = t & 31;
    int u8 = g_mask_u8;
    __shared__ int wcnt[8];
    __shared__ int woff[9];

    // Pass 1: each warp counts keeps in its 256-l segment; record keep bits.
    unsigned keepbits[8];   // per-lane: bit r set if l = w*256 + r*32 + lane kept
    int cnt = 0;
    unsigned mykeep = 0;
#pragma unroll
    for (int r = 0; r < 8; r++) {
        int l = w * 256 + r * 32 + lane;
        int idx = b * L + l;
        bool keep = u8 ? (m8[idx] == 0) : (m32[idx] == 0);
        if (!keep) g_scores[idx] = MIN_VALUE;     // pre-fill masked slots
        unsigned m = __ballot_sync(FULL, keep);
        keepbits[r] = m;
        if (keep) mykeep |= (1u << r);
        cnt += __popc(m);
    }
    if (lane == 0) wcnt[w] = cnt;
    __syncthreads();
    if (t == 0) {
        woff[0] = 0;
#pragma unroll
        for (int i = 0; i < 8; i++) woff[i + 1] = woff[i] + wcnt[i];
        g_lcnt[b] = woff[8];
    }
    __syncthreads();

    // Pass 2: write indices at global positions.
    int base = woff[w];
#pragma unroll
    for (int r = 0; r < 8; r++) {
        unsigned m = keepbits[r];
        if (mykeep & (1u << r)) {
            int pos = base + __popc(m & ((1u << lane) - 1u));
            g_lidx[b * L + pos] = w * 256 + r * 32 + lane;
        }
        base += __popc(m);
    }
}

// Accurate fast tanh: 2 MUFU (EX2 + RCP) + FMAs, rel err ~1e-7.
__device__ __forceinline__ float tanh_fast(float x) {
    float ax = fabsf(x);
    float e  = __expf(-2.0f * ax);
    float t  = __fdividef(1.0f - e, 1.0f + e);
    return copysignf(t, x);
}

// ---------------------------------------------------------------------------
// scores over the COMPACT list only: block jg covers list slots jg*8..jg*8+7
// of batch b. Blocks past the count exit on one uniform load.
// ---------------------------------------------------------------------------
__global__ void k_scores(const float* __restrict__ p,
                         const float* __restrict__ Wa,
                         const float* __restrict__ ba) {
    int b  = blockIdx.x >> 8;
    int jg = blockIdx.x & 255;
    int cnt = g_lcnt[b];
    if (jg * 8 >= cnt) return;

    __shared__ __align__(16) float sa[A];
    __shared__ __align__(16) float sw[A];
    int t = threadIdx.x;
    sa[t]       = g_att_h[b * A + t];
    sa[t + 256] = g_att_h[b * A + t + 256];
    sw[t]       = Wa[t];
    sw[t + 256] = Wa[t + 256];
    __syncthreads();

    int w = t >> 5, lane = t & 31;
    int j = jg * 8 + w;
    if (j >= cnt) return;
    int l = 0;
    if (lane == 0) l = g_lidx[b * L + j];
    l = __shfl_sync(FULL, l, 0);
    int idx = b * L + l;

    const float4* p4 = (const float4*)(p + (size_t)idx * A);
    const float4* a4 = (const float4*)sa;
    const float4* w4 = (const float4*)sw;

    float4 pv[4];
#pragma unroll
    for (int j2 = 0; j2 < 4; j2++) pv[j2] = ldcs4(p4 + lane + j2 * 32);

    float acc = 0.f;
#pragma unroll
    for (int j2 = 0; j2 < 4; j2++) {
        int i = lane + j2 * 32;
        float4 av = a4[i], wv = w4[i];
        acc += tanh_fast(pv[j2].x + av.x) * wv.x;
        acc += tanh_fast(pv[j2].y + av.y) * wv.y;
        acc += tanh_fast(pv[j2].z + av.z) * wv.z;
        acc += tanh_fast(pv[j2].w + av.w) * wv.w;
    }
#pragma unroll
    for (int o = 16; o > 0; o >>= 1) acc += __shfl_down_sync(FULL, acc, o);
    if (lane == 0) g_scores[idx] = acc + ba[0];
}

// ---------------------------------------------------------------------------
// k_smax1: partial softmax stats. grid (SC, BATCH); each block reduces 256
// scores to (local max, local sum(exp(s-lmx))).
// ---------------------------------------------------------------------------
__global__ void k_smax1() {
    int ch = blockIdx.x, b = blockIdx.y, t = threadIdx.x;
    int w = t >> 5, lane = t & 31;
    __shared__ float red[8];

    float s = g_scores[b * L + ch * SLEN + t];
    float mx = s;
#pragma unroll
    for (int o = 16; o > 0; o >>= 1) mx = fmaxf(mx, __shfl_xor_sync(FULL, mx, o));
    if (lane == 0) red[w] = mx;
    __syncthreads();
    if (t == 0) {
        float v = red[0];
#pragma unroll
        for (int i = 1; i < 8; i++) v = fmaxf(v, red[i]);
        red[0] = v;
    }
    __syncthreads();
    mx = red[0];
    __syncthreads();

    float e = __expf(s - mx);
#pragma unroll
    for (int o = 16; o > 0; o >>= 1) e += __shfl_xor_sync(FULL, e, o);
    if (lane == 0) red[w] = e;
    __syncthreads();
    if (t == 0) {
        float v = 0.f;
#pragma unroll
        for (int i = 0; i < 8; i++) v += red[i];
        g_pmx[b * SC + ch] = mx;
        g_ps[b * SC + ch]  = v;
    }
}

// ---------------------------------------------------------------------------
// k_wsum: per-(chunk, b) weighted-sum partials with zero-weight row skipping,
// split-softmax recombine in the prologue, and the final cross-chunk reduce
// fused in via a per-b completion counter (last block reduces + self-resets).
// Masked l's have w = exp(-1e8 - mx)*inv == 0.0f exactly (underflow; the
// reference contributes the same 0.0f) -> skipping is bit-exact.
//
// Release ordering (the R7 bug): every thread stores its partial lane, then
// __threadfence() orders each thread's own store, then __syncthreads()
// guarantees ALL threads' fenced stores are globally visible before thread 0
// publishes completion via atomicAdd. Fence->barrier->atomic, in that order.
// ---------------------------------------------------------------------------
__global__ void k_wsum(const float* __restrict__ af, float* __restrict__ out) {
    int c = blockIdx.x, b = blockIdx.y, t = threadIdx.x;
    __shared__ float swraw[LC];
    __shared__ float swv[LC];
    __shared__ int   sidx[LC];
    __shared__ int   scount;
    __shared__ float s_mx, s_inv;
    __shared__ int   s_ticket;

    // Recombine split-softmax partials (8 values).
    if (t == 0) {
        float mx = g_pmx[b * SC];
#pragma unroll
        for (int i = 1; i < SC; i++) mx = fmaxf(mx, g_pmx[b * SC + i]);
        float sum = 0.f;
#pragma unroll
        for (int i = 0; i < SC; i++)
            sum += g_ps[b * SC + i] * __expf(g_pmx[b * SC + i] - mx);
        s_mx  = mx;
        s_inv = 1.0f / sum;
    }
    __syncthreads();

    int lbase = b * L + c * LC;
    if (t < LC) {
        float s = g_scores[lbase + t];
        swraw[t] = __expf(s - s_mx) * s_inv;
    }
    __syncthreads();

    if (t < 32) {
        int base = 0;
#pragma unroll
        for (int k = 0; k < LC; k += 32) {
            float w = swraw[k + t];
            unsigned m = __ballot_sync(FULL, w != 0.f);
            if (w != 0.f) {
                int pos = base + __popc(m & ((1u << t) - 1u));
                swv[pos]  = w;
                sidx[pos] = k + t;
            }
            base += __popc(m);
        }
        if (t == 0) scount = base;
    }
    __syncthreads();

    const float4* a4 = (const float4*)(af + (size_t)lbase * R);
    float4 acc = make_float4(0.f, 0.f, 0.f, 0.f);
    int n = scount;
    int j = 0;
    for (; j + 4 <= n; j += 4) {
        float w0 = swv[j],     w1 = swv[j + 1];
        float w2 = swv[j + 2], w3 = swv[j + 3];
        float4 v0 = ldcs4(a4 + (size_t)sidx[j]     * (R / 4) + t);
        float4 v1 = ldcs4(a4 + (size_t)sidx[j + 1] * (R / 4) + t);
        float4 v2 = ldcs4(a4 + (size_t)sidx[j + 2] * (R / 4) + t);
        float4 v3 = ldcs4(a4 + (size_t)sidx[j + 3] * (R / 4) + t);
        acc.x += w0 * v0.x; acc.y += w0 * v0.y; acc.z += w0 * v0.z; acc.w += w0 * v0.w;
        acc.x += w1 * v1.x; acc.y += w1 * v1.y; acc.z += w1 * v1.z; acc.w += w1 * v1.w;
        acc.x += w2 * v2.x; acc.y += w2 * v2.y; acc.z += w2 * v2.z; acc.w += w2 * v2.w;
        acc.x += w3 * v3.x; acc.y += w3 * v3.y; acc.z += w3 * v3.z; acc.w += w3 * v3.w;
    }
    for (; j < n; j++) {
        float w  = swv[j];
        float4 v = ldcs4(a4 + (size_t)sidx[j] * (R / 4) + t);
        acc.x += w * v.x; acc.y += w * v.y; acc.z += w * v.z; acc.w += w * v.w;
    }
    ((float4*)(g_part + ((size_t)c * BATCH + b) * R))[t] = acc;

    // Fused final reduce with CORRECT release ordering:
    __threadfence();     // each thread: my store is ordered before what follows
    __syncthreads();     // all threads fenced => all partial lanes visible
    if (t == 0) s_ticket = atomicAdd(&g_cnt[b], 1);
    __syncthreads();
    if (s_ticket == CH - 1) {
        float4 s = make_float4(0.f, 0.f, 0.f, 0.f);
#pragma unroll
        for (int cc = 0; cc < CH; cc++) {
            float4 v = ldcg4((const float4*)(g_part + ((size_t)cc * BATCH + b) * R) + t);
            s.x += v.x; s.y += v.y; s.z += v.z; s.w += v.w;
        }
        ((float4*)(out + (size_t)b * R))[t] = s;
        if (t == 0) g_cnt[b] = 0;   // self-reset for next launch/replay
    }
}

// ---------------------------------------------------------------------------
extern "C" void kernel_launch(void* const* d_in, const int* in_sizes, int n_in,
                              void* d_out, int out_size) {
    const float* h    = (const float*)d_in[0];
    const float* af   = (const float*)d_in[1];
    const float* p    = (const float*)d_in[2];
    const void*  mask = d_in[3];
    const float* Wh   = (const float*)d_in[4];
    const float* bh   = (const float*)d_in[5];
    const float* Wa   = (const float*)d_in[6];
    const float* ba   = (const float*)d_in[7];
    float* out = (float*)d_out;

    k_att_h<<<257, 256>>>(h, Wh, bh, (const unsigned int*)mask);
    k_compact<<<BATCH, 256>>>((const unsigned char*)mask, (const int*)mask);
    k_scores<<<8192, 256>>>(p, Wa, ba);
    k_smax1<<<dim3(SC, BATCH), 256>>>();
    k_wsum<<<dim3(CH, BATCH), 256>>>(af, out);
}